// round 12
// baseline (speedup 1.0000x reference)
#include <cuda_runtime.h>
#include <cuda_bf16.h>

// CompositeLoss fused single-kernel, R10: packed f32x2 math (FFMA2/FMUL2/FADD2)
// for the element chain + moment accumulation; scalar MUFU for ex2/rcp/lg2.

#define PLANES   320          // B*C = 16*20
#define SUBS     8            // blocks per plane
#define THREADS  256          // 8 warps
#define F4_PLANE 16384        // HW/4
#define NTOT_D   20971520.0

typedef unsigned long long u64;

// Per-plane moments: [mass, sty, stx, sp, spy, spx, spyy, spxx]
__device__ float        g_plane[PLANES * 8];
// Global sums: [fl(log2-scale), sum (x-t)^2, sum |x|]
__device__ double       g_glob[3];
__device__ unsigned int g_count;

__device__ __forceinline__ float frcp(float x) {
    float r; asm("rcp.approx.f32 %0, %1;" : "=f"(r) : "f"(x)); return r;
}
__device__ __forceinline__ float fex2(float x) {
    float r; asm("ex2.approx.f32 %0, %1;" : "=f"(r) : "f"(x)); return r;
}
__device__ __forceinline__ float flg2(float x) {
    float r; asm("lg2.approx.f32 %0, %1;" : "=f"(r) : "f"(x)); return r;
}
__device__ __forceinline__ u64 pk(float lo, float hi) {
    u64 r; asm("mov.b64 %0, {%1, %2};" : "=l"(r) : "f"(lo), "f"(hi)); return r;
}
__device__ __forceinline__ void upk(float& lo, float& hi, u64 v) {
    asm("mov.b64 {%0, %1}, %2;" : "=f"(lo), "=f"(hi) : "l"(v));
}
__device__ __forceinline__ u64 fma2(u64 a, u64 b, u64 c) {
    u64 r; asm("fma.rn.f32x2 %0, %1, %2, %3;" : "=l"(r) : "l"(a), "l"(b), "l"(c)); return r;
}
__device__ __forceinline__ u64 mul2(u64 a, u64 b) {
    u64 r; asm("mul.rn.f32x2 %0, %1, %2;" : "=l"(r) : "l"(a), "l"(b)); return r;
}
__device__ __forceinline__ u64 add2(u64 a, u64 b) {
    u64 r; asm("add.rn.f32x2 %0, %1, %2;" : "=l"(r) : "l"(a), "l"(b)); return r;
}

struct Consts {
    u64 CL2;      // (-log2e, -log2e)
    u64 ONE2, NEGONE2, NEG2, NEGHALF2, C075_2;
    u64 W01, W23, W49;
};

struct PAcc {
    u64 fl2, sq2;
    u64 P2, Q1_2, Q2_2;
    u64 T2, TQ1_2;
    u64 spy2, spyy2, sty2;
    float ab;
};

// One packed pair (2 elements): focal/sparsity chain. Returns packed p (r2).
__device__ __forceinline__ u64 pair_core(float xl, float xh, u64 t2,
                                         const Consts& C, PAcc& A)
{
    const u64 x2 = pk(xl, xh);
    const u64 m2 = mul2(x2, C.CL2);                 // -x*log2(e)
    float ml, mh; upk(ml, mh, m2);
    const float sl = fex2(ml) + 1.0f;               // 1 + e^{-x}
    const float sh = fex2(mh) + 1.0f;
    const u64 r2 = pk(frcp(sl), frcp(sh));          // p = sigmoid(x)
    const u64 L2 = pk(flg2(sl), flg2(sh));          // -lg2(p)
    const u64 tm2  = fma2(t2, m2, L2);              // t*m + L
    const u64 lg2v = fma2(tm2, C.NEGONE2, m2);      // lg2(pt) = m - (t*m+L)
    const u64 k2   = fma2(r2, C.NEG2, C.ONE2);      // 1 - 2p
    const u64 u2   = fma2(t2, k2, r2);              // 1 - pt
    const u64 a2   = fma2(t2, C.NEGHALF2, C.C075_2);// alpha_t
    const u64 uu2  = mul2(u2, u2);
    const u64 au2  = mul2(a2, uu2);
    A.fl2 = fma2(au2, lg2v, A.fl2);                 // (negative), *ln2 at end
    const u64 dd2 = fma2(t2, C.NEGONE2, x2);        // x - t
    A.sq2 = fma2(dd2, dd2, A.sq2);
    A.ab += fabsf(xl);
    A.ab += fabsf(xh);
    return r2;
}

__global__ __launch_bounds__(THREADS, 3) void composite_kernel(
    const float4* __restrict__ pred, const float4* __restrict__ tgt,
    float* __restrict__ out, int out_size)
{
    const int plane = blockIdx.x >> 3;
    const int sub   = blockIdx.x & 7;
    const int half  = sub & 1;          // column half: 0 -> [0,128), 1 -> [128,256)
    const int rb    = sub >> 1;         // row block of 64 rows
    const int warp  = threadIdx.x >> 5;
    const int lane  = threadIdx.x & 31;

    const int   row0 = rb * 64 + warp * 8;              // 8 rows per warp
    const float x0   = (float)(half * 128 + lane * 4);  // base column of this thread

    const int base = plane * F4_PLANE + row0 * 64 + half * 32 + lane;
    const float4* __restrict__ pp = pred + base;
    const float4* __restrict__ tp = tgt  + base;

    Consts C;
    C.CL2      = pk(-1.4426950408889634f, -1.4426950408889634f);
    C.ONE2     = pk(1.0f, 1.0f);
    C.NEGONE2  = pk(-1.0f, -1.0f);
    C.NEG2     = pk(-2.0f, -2.0f);
    C.NEGHALF2 = pk(-0.5f, -0.5f);
    C.C075_2   = pk(0.75f, 0.75f);
    C.W01      = pk(0.0f, 1.0f);
    C.W23      = pk(2.0f, 3.0f);
    C.W49      = pk(4.0f, 9.0f);

    PAcc A;
    A.fl2 = A.sq2 = A.P2 = A.Q1_2 = A.Q2_2 = 0ull;
    A.T2 = A.TQ1_2 = A.spy2 = A.spyy2 = A.sty2 = 0ull;
    A.ab = 0.0f;

    #pragma unroll
    for (int r = 0; r < 8; r++) {
        const float4 pv = pp[r * 64];
        const float4 tv = tp[r * 64];

        const u64 t2a = pk(tv.x, tv.y);
        const u64 t2b = pk(tv.z, tv.w);
        const u64 r2a = pair_core(pv.x, pv.y, t2a, C, A);
        const u64 r2b = pair_core(pv.z, pv.w, t2b, C, A);

        // p/t group moments (lane semantics: lo = j even, hi = j odd)
        const u64 ps2 = add2(r2a, r2b);
        const u64 ts2 = add2(t2a, t2b);
        A.P2    = add2(A.P2, ps2);
        A.T2    = add2(A.T2, ts2);
        A.Q1_2  = add2(A.Q1_2, fma2(r2b, C.W23, mul2(r2a, C.W01)));
        A.Q2_2  = add2(A.Q2_2, fma2(r2b, C.W49, mul2(r2a, C.W01)));
        A.TQ1_2 = add2(A.TQ1_2, fma2(t2b, C.W23, mul2(t2a, C.W01)));

        const float y = (float)(row0 + r);
        const u64 Y2  = pk(y, y);
        const u64 YY2 = pk(y * y, y * y);
        A.spy2  = fma2(ps2, Y2, A.spy2);
        A.spyy2 = fma2(ps2, YY2, A.spyy2);
        A.sty2  = fma2(ts2, Y2, A.sty2);
    }

    // ---- horizontal fold of packed accumulators ----
    float lo, hi;
    upk(lo, hi, A.fl2);   const float fl   = lo + hi;
    upk(lo, hi, A.sq2);   const float sq   = lo + hi;
    upk(lo, hi, A.P2);    const float P    = lo + hi;
    upk(lo, hi, A.Q1_2);  const float Q1   = lo + hi;
    upk(lo, hi, A.Q2_2);  const float Q2   = lo + hi;
    upk(lo, hi, A.T2);    const float T    = lo + hi;
    upk(lo, hi, A.TQ1_2); const float TQ1  = lo + hi;
    upk(lo, hi, A.spy2);  const float spy  = lo + hi;
    upk(lo, hi, A.spyy2); const float spyy = lo + hi;
    upk(lo, hi, A.sty2);  const float sty  = lo + hi;

    // Per-thread x folds: x = x0 + j
    const float sp   = P;
    const float spx  = fmaf(x0, P, Q1);
    const float spxx = fmaf(x0 * x0, P, fmaf(2.0f * x0, Q1, Q2));
    const float mass = T;
    const float stx  = fmaf(x0, T, TQ1);

    // ---- block reduction of 11 values ----
    float vals[11] = {fl, sq, A.ab, mass, sty, stx, sp, spy, spx, spyy, spxx};
    #pragma unroll
    for (int offm = 16; offm > 0; offm >>= 1) {
        #pragma unroll
        for (int k = 0; k < 11; k++)
            vals[k] += __shfl_down_sync(0xffffffffu, vals[k], offm);
    }
    __shared__ float smem[THREADS / 32][11];
    if (lane == 0) {
        #pragma unroll
        for (int k = 0; k < 11; k++) smem[warp][k] = vals[k];
    }
    __syncthreads();

    __shared__ bool s_last;
    if (threadIdx.x == 0) {
        float rr[11];
        #pragma unroll
        for (int k = 0; k < 11; k++) rr[k] = smem[0][k];
        for (int w = 1; w < THREADS / 32; w++)
            #pragma unroll
            for (int k = 0; k < 11; k++) rr[k] += smem[w][k];

        atomicAdd(&g_glob[0], (double)rr[0]);
        atomicAdd(&g_glob[1], (double)rr[1]);
        atomicAdd(&g_glob[2], (double)rr[2]);
        float* Pp = &g_plane[plane * 8];
        #pragma unroll
        for (int k = 0; k < 8; k++) atomicAdd(&Pp[k], rr[3 + k]);

        __threadfence();
        const unsigned cc = atomicAdd(&g_count, 1u);
        s_last = (cc == gridDim.x - 1);
    }
    __syncthreads();
    if (!s_last) return;

    // ---- last block: finalize + reset ----
    __threadfence();
    __shared__ float s_conc;
    __shared__ int   s_nv;
    if (threadIdx.x == 0) { s_conc = 0.f; s_nv = 0; }
    __syncthreads();

    for (int i = threadIdx.x; i < PLANES; i += THREADS) {
        const float* Pp = &g_plane[i * 8];
        const float m = Pp[0];
        if (m > 0.0f) {
            const float cy = Pp[1] / m;
            const float cx = Pp[2] / m;
            const float num = Pp[6] - 2.0f * cy * Pp[4] + cy * cy * Pp[3]
                            + Pp[7] - 2.0f * cx * Pp[5] + cx * cx * Pp[3];
            atomicAdd(&s_conc, num * (1.0f / 65536.0f));
            atomicAdd(&s_nv, 1);
        }
    }
    __syncthreads();

    if (threadIdx.x == 0) {
        const double N = NTOT_D;
        const float focal    = (float)(-0.6931471805599453 * g_glob[0] / N);
        const float sparsity = (float)((g_glob[1] + g_glob[2]) / N);
        const float conc     = (s_nv > 0) ? (s_conc / (float)s_nv) : 0.0f;
        out[0] = focal + 0.8f * sparsity + 1.5f * conc;
        if (out_size >= 4) { out[1] = focal; out[2] = sparsity; out[3] = conc; }
    }
    __syncthreads();

    // reset accumulators for next launch (graph replay)
    for (int i = threadIdx.x; i < PLANES * 8; i += THREADS) g_plane[i] = 0.0f;
    if (threadIdx.x < 3) g_glob[threadIdx.x] = 0.0;
    if (threadIdx.x == 0) g_count = 0u;
}

extern "C" void kernel_launch(void* const* d_in, const int* in_sizes, int n_in,
                              void* d_out, int out_size) {
    const float4* pred = (const float4*)d_in[0];
    const float4* tgt  = (const float4*)d_in[1];
    composite_kernel<<<PLANES * SUBS, THREADS>>>(pred, tgt, (float*)d_out, out_size);
}

// round 13
// speedup vs baseline: 1.0087x; 1.0087x over previous
#include <cuda_runtime.h>
#include <cuda_bf16.h>

// CompositeLoss fused single-kernel, R12: packed f32x2 math at a 64-reg
// budget (4 CTAs/SM). Raw packed moment sums with fold-time j-weighting,
// scalar FMUL-imm for the log2e scale, 5 packed constants only.

#define PLANES   320          // B*C = 16*20
#define SUBS     8            // blocks per plane
#define THREADS  256          // 8 warps
#define F4_PLANE 16384        // HW/4
#define NTOT_D   20971520.0

typedef unsigned long long u64;

// Per-plane moments: [mass, sty, stx, sp, spy, spx, spyy, spxx]
__device__ float        g_plane[PLANES * 8];
// Global sums: [fl(log2-scale), sum (x-t)^2, sum |x|]
__device__ double       g_glob[3];
__device__ unsigned int g_count;

__device__ __forceinline__ float frcp(float x) {
    float r; asm("rcp.approx.f32 %0, %1;" : "=f"(r) : "f"(x)); return r;
}
__device__ __forceinline__ float fex2(float x) {
    float r; asm("ex2.approx.f32 %0, %1;" : "=f"(r) : "f"(x)); return r;
}
__device__ __forceinline__ float flg2(float x) {
    float r; asm("lg2.approx.f32 %0, %1;" : "=f"(r) : "f"(x)); return r;
}
__device__ __forceinline__ u64 pk(float lo, float hi) {
    u64 r; asm("mov.b64 %0, {%1, %2};" : "=l"(r) : "f"(lo), "f"(hi)); return r;
}
__device__ __forceinline__ void upk(float& lo, float& hi, u64 v) {
    asm("mov.b64 {%0, %1}, %2;" : "=f"(lo), "=f"(hi) : "l"(v));
}
__device__ __forceinline__ u64 fma2(u64 a, u64 b, u64 c) {
    u64 r; asm("fma.rn.f32x2 %0, %1, %2, %3;" : "=l"(r) : "l"(a), "l"(b), "l"(c)); return r;
}
__device__ __forceinline__ u64 mul2(u64 a, u64 b) {
    u64 r; asm("mul.rn.f32x2 %0, %1, %2;" : "=l"(r) : "l"(a), "l"(b)); return r;
}
__device__ __forceinline__ u64 add2(u64 a, u64 b) {
    u64 r; asm("add.rn.f32x2 %0, %1, %2;" : "=l"(r) : "l"(a), "l"(b)); return r;
}

struct Consts { u64 ONE2, NEGONE2, NEG2, NEGHALF2, C075_2; };

struct PAcc {
    u64 fl2, sq2;
    u64 Pa2, Pb2, Ta2, Tb2;      // raw packed sums; j-weights applied at fold
    u64 spy2, spyy2, sty2;
    float ab;
};

// One packed pair (2 elements). Returns packed p.
__device__ __forceinline__ u64 pair_core(float xl, float xh, u64 t2,
                                         const Consts& C, PAcc& A)
{
    // scalar prologue: FMUL-imm (rt=1) + MUFU
    const float ml = xl * -1.4426950408889634f;
    const float mh = xh * -1.4426950408889634f;
    const float sl = fex2(ml) + 1.0f;               // 1 + e^{-x}
    const float sh = fex2(mh) + 1.0f;
    const u64 r2 = pk(frcp(sl), frcp(sh));          // p = sigmoid(x)
    const u64 L2 = pk(flg2(sl), flg2(sh));          // -lg2(p)
    const u64 m2 = pk(ml, mh);
    const u64 x2 = pk(xl, xh);

    const u64 tm2  = fma2(t2, m2, L2);              // t*m + L
    const u64 lg2v = fma2(tm2, C.NEGONE2, m2);      // lg2(pt) = m - (t*m+L)
    const u64 k2   = fma2(r2, C.NEG2, C.ONE2);      // 1 - 2p
    const u64 u2   = fma2(t2, k2, r2);              // 1 - pt
    const u64 a2   = fma2(t2, C.NEGHALF2, C.C075_2);// alpha_t
    const u64 uu2  = mul2(u2, u2);
    const u64 au2  = mul2(a2, uu2);
    A.fl2 = fma2(au2, lg2v, A.fl2);                 // (negative), *ln2 at end
    const u64 dd2 = fma2(t2, C.NEGONE2, x2);        // x - t
    A.sq2 = fma2(dd2, dd2, A.sq2);
    A.ab += fabsf(xl);
    A.ab += fabsf(xh);
    return r2;
}

__global__ __launch_bounds__(THREADS, 4) void composite_kernel(
    const float4* __restrict__ pred, const float4* __restrict__ tgt,
    float* __restrict__ out, int out_size)
{
    const int plane = blockIdx.x >> 3;
    const int sub   = blockIdx.x & 7;
    const int half  = sub & 1;          // column half: 0 -> [0,128), 1 -> [128,256)
    const int rb    = sub >> 1;         // row block of 64 rows
    const int warp  = threadIdx.x >> 5;
    const int lane  = threadIdx.x & 31;

    const int   row0 = rb * 64 + warp * 8;              // 8 rows per warp
    const float x0   = (float)(half * 128 + lane * 4);  // base column of this thread

    const int base = plane * F4_PLANE + row0 * 64 + half * 32 + lane;
    const float4* __restrict__ pp = pred + base;
    const float4* __restrict__ tp = tgt  + base;

    Consts C;
    C.ONE2     = pk(1.0f, 1.0f);
    C.NEGONE2  = pk(-1.0f, -1.0f);
    C.NEG2     = pk(-2.0f, -2.0f);
    C.NEGHALF2 = pk(-0.5f, -0.5f);
    C.C075_2   = pk(0.75f, 0.75f);

    PAcc A;
    A.fl2 = A.sq2 = 0ull;
    A.Pa2 = A.Pb2 = A.Ta2 = A.Tb2 = 0ull;
    A.spy2 = A.spyy2 = A.sty2 = 0ull;
    A.ab = 0.0f;

    #pragma unroll
    for (int r = 0; r < 8; r++) {
        const float4 pv = pp[r * 64];
        const float4 tv = tp[r * 64];

        const u64 t2a = pk(tv.x, tv.y);
        const u64 t2b = pk(tv.z, tv.w);
        const u64 r2a = pair_core(pv.x, pv.y, t2a, C, A);
        const u64 r2b = pair_core(pv.z, pv.w, t2b, C, A);

        A.Pa2 = add2(A.Pa2, r2a);
        A.Pb2 = add2(A.Pb2, r2b);
        A.Ta2 = add2(A.Ta2, t2a);
        A.Tb2 = add2(A.Tb2, t2b);

        const u64 ps2 = add2(r2a, r2b);
        const u64 ts2 = add2(t2a, t2b);
        const float y = (float)(row0 + r);
        const u64 Y2  = pk(y, y);
        const u64 YY2 = pk(y * y, y * y);
        A.spy2  = fma2(ps2, Y2, A.spy2);
        A.spyy2 = fma2(ps2, YY2, A.spyy2);
        A.sty2  = fma2(ts2, Y2, A.sty2);
    }

    // ---- fold packed accumulators (lane lo = j in {0,2}, hi = j in {1,3}) ----
    float lo, hi, pal, pah, pbl, pbh, tal, tah, tbl, tbh;
    upk(lo, hi, A.fl2);   const float fl = lo + hi;
    upk(lo, hi, A.sq2);   const float sq = lo + hi;
    upk(pal, pah, A.Pa2);
    upk(pbl, pbh, A.Pb2);
    upk(tal, tah, A.Ta2);
    upk(tbl, tbh, A.Tb2);
    upk(lo, hi, A.spy2);  const float spy  = lo + hi;
    upk(lo, hi, A.spyy2); const float spyy = lo + hi;
    upk(lo, hi, A.sty2);  const float sty  = lo + hi;

    const float P   = (pal + pah) + (pbl + pbh);
    const float Q1  = fmaf(3.0f, pbh, fmaf(2.0f, pbl, pah));
    const float Q2  = fmaf(9.0f, pbh, fmaf(4.0f, pbl, pah));
    const float T   = (tal + tah) + (tbl + tbh);
    const float TQ1 = fmaf(3.0f, tbh, fmaf(2.0f, tbl, tah));

    // Per-thread x folds: x = x0 + j
    const float sp   = P;
    const float spx  = fmaf(x0, P, Q1);
    const float spxx = fmaf(x0 * x0, P, fmaf(2.0f * x0, Q1, Q2));
    const float mass = T;
    const float stx  = fmaf(x0, T, TQ1);

    // ---- block reduction of 11 values ----
    float vals[11] = {fl, sq, A.ab, mass, sty, stx, sp, spy, spx, spyy, spxx};
    #pragma unroll
    for (int offm = 16; offm > 0; offm >>= 1) {
        #pragma unroll
        for (int k = 0; k < 11; k++)
            vals[k] += __shfl_down_sync(0xffffffffu, vals[k], offm);
    }
    __shared__ float smem[THREADS / 32][11];
    if (lane == 0) {
        #pragma unroll
        for (int k = 0; k < 11; k++) smem[warp][k] = vals[k];
    }
    __syncthreads();

    __shared__ bool s_last;
    if (threadIdx.x == 0) {
        float rr[11];
        #pragma unroll
        for (int k = 0; k < 11; k++) rr[k] = smem[0][k];
        for (int w = 1; w < THREADS / 32; w++)
            #pragma unroll
            for (int k = 0; k < 11; k++) rr[k] += smem[w][k];

        atomicAdd(&g_glob[0], (double)rr[0]);
        atomicAdd(&g_glob[1], (double)rr[1]);
        atomicAdd(&g_glob[2], (double)rr[2]);
        float* Pp = &g_plane[plane * 8];
        #pragma unroll
        for (int k = 0; k < 8; k++) atomicAdd(&Pp[k], rr[3 + k]);

        __threadfence();
        const unsigned cc = atomicAdd(&g_count, 1u);
        s_last = (cc == gridDim.x - 1);
    }
    __syncthreads();
    if (!s_last) return;

    // ---- last block: finalize + reset ----
    __threadfence();
    __shared__ float s_conc;
    __shared__ int   s_nv;
    if (threadIdx.x == 0) { s_conc = 0.f; s_nv = 0; }
    __syncthreads();

    for (int i = threadIdx.x; i < PLANES; i += THREADS) {
        const float* Pp = &g_plane[i * 8];
        const float m = Pp[0];
        if (m > 0.0f) {
            const float cy = Pp[1] / m;
            const float cx = Pp[2] / m;
            const float num = Pp[6] - 2.0f * cy * Pp[4] + cy * cy * Pp[3]
                            + Pp[7] - 2.0f * cx * Pp[5] + cx * cx * Pp[3];
            atomicAdd(&s_conc, num * (1.0f / 65536.0f));
            atomicAdd(&s_nv, 1);
        }
    }
    __syncthreads();

    if (threadIdx.x == 0) {
        const double N = NTOT_D;
        const float focal    = (float)(-0.6931471805599453 * g_glob[0] / N);
        const float sparsity = (float)((g_glob[1] + g_glob[2]) / N);
        const float conc     = (s_nv > 0) ? (s_conc / (float)s_nv) : 0.0f;
        out[0] = focal + 0.8f * sparsity + 1.5f * conc;
        if (out_size >= 4) { out[1] = focal; out[2] = sparsity; out[3] = conc; }
    }
    __syncthreads();

    // reset accumulators for next launch (graph replay)
    for (int i = threadIdx.x; i < PLANES * 8; i += THREADS) g_plane[i] = 0.0f;
    if (threadIdx.x < 3) g_glob[threadIdx.x] = 0.0;
    if (threadIdx.x == 0) g_count = 0u;
}

extern "C" void kernel_launch(void* const* d_in, const int* in_sizes, int n_in,
                              void* d_out, int out_size) {
    const float4* pred = (const float4*)d_in[0];
    const float4* tgt  = (const float4*)d_in[1];
    composite_kernel<<<PLANES * SUBS, THREADS>>>(pred, tgt, (float*)d_out, out_size);
}

// round 14
// speedup vs baseline: 1.1192x; 1.1095x over previous
#include <cuda_runtime.h>
#include <cuda_bf16.h>

// CompositeLoss fused single-kernel, R13: scalar R8 structure + tanh-based
// sigmoid => 2 MUFU/element (tanh, lg2) instead of 3 (ex2, rcp, lg2).
// MUFU pipe was the hidden ~60%-utilized pipe across all prior variants.

#define PLANES   320          // B*C = 16*20
#define SUBS     8            // blocks per plane
#define THREADS  256          // 8 warps
#define F4_PLANE 16384        // HW/4
#define NTOT_D   20971520.0

// Per-plane moments: [mass, sty, stx, sp, spy, spx, spyy, spxx]
__device__ float        g_plane[PLANES * 8];
// Global sums: [fl(log2-scale), sum (x-t)^2, sum |x|]
__device__ double       g_glob[3];
__device__ unsigned int g_count;

__device__ __forceinline__ float ftanh(float x) {
    float r; asm("tanh.approx.f32 %0, %1;" : "=f"(r) : "f"(x)); return r;
}
__device__ __forceinline__ float flg2(float x) {
    float r; asm("lg2.approx.f32 %0, %1;" : "=f"(r) : "f"(x)); return r;
}

// One float4 (4 elements): focal/sparsity terms + group moments.
__device__ __forceinline__ void grp4(const float4 pv, const float4 tv,
                                     float& fl, float& sq, float& ab,
                                     float& psum, float& q1, float& q2,
                                     float& tsum, float& tq1)
{
    const float xv[4] = {pv.x, pv.y, pv.z, pv.w};
    const float tt[4] = {tv.x, tv.y, tv.z, tv.w};
    float p[4];
    #pragma unroll
    for (int j = 0; j < 4; j++) {
        const float x = xv[j];
        const float t = tt[j];                        // 0.0f or 1.0f
        const float th = ftanh(x * 0.5f);             // MUFU.TANH
        const float r  = fmaf(0.5f, th, 0.5f);        // p = sigmoid(x)
        const float m  = x * -1.4426950408889634f;    // lg2(e^{-x})
        const float L  = flg2(r);                     // lg2(p)  (MUFU.LG2)
        const float lgm1 = L + m;                     // lg2(1-p) = lg2(p*e^{-x})
        const float lg = fmaf(t, -m, lgm1);           // lg2(pt): t=1 -> L, t=0 -> L+m
        const float u  = fmaf(t, -th, r);             // 1-pt: t=1 -> 1-p, t=0 -> p
        const float a  = fmaf(t, -0.5f, 0.75f);       // alpha_t
        fl = fmaf(a * (u * u), lg, fl);               // (negative), *ln2 at end
        const float dd = x - t;
        sq = fmaf(dd, dd, sq);
        ab += fabsf(x);
        p[j] = r;
    }
    psum += (p[0] + p[1]) + (p[2] + p[3]);
    q1   += fmaf(3.0f, p[3], fmaf(2.0f, p[2], p[1]));
    q2   += fmaf(9.0f, p[3], fmaf(4.0f, p[2], p[1]));
    tsum += (tt[0] + tt[1]) + (tt[2] + tt[3]);
    tq1  += fmaf(3.0f, tt[3], fmaf(2.0f, tt[2], tt[1]));
}

__global__ __launch_bounds__(THREADS, 4) void composite_kernel(
    const float4* __restrict__ pred, const float4* __restrict__ tgt,
    float* __restrict__ out, int out_size)
{
    const int plane = blockIdx.x >> 3;
    const int sub   = blockIdx.x & 7;
    const int half  = sub & 1;          // column half: 0 -> [0,128), 1 -> [128,256)
    const int rb    = sub >> 1;         // row block of 64 rows
    const int warp  = threadIdx.x >> 5;
    const int lane  = threadIdx.x & 31;

    const int   row0 = rb * 64 + warp * 8;              // 8 rows per warp
    const float x0   = (float)(half * 128 + lane * 4);  // base column of this thread

    const int base = plane * F4_PLANE + row0 * 64 + half * 32 + lane;
    const float4* __restrict__ pp = pred + base;
    const float4* __restrict__ tp = tgt  + base;

    float fl = 0.f, sq = 0.f, ab = 0.f;
    float P = 0.f, Q1 = 0.f, Q2 = 0.f;
    float spy = 0.f, spyy = 0.f;
    float T = 0.f, TQ1 = 0.f, sty = 0.f;

    float y = (float)row0;
    #pragma unroll
    for (int r = 0; r < 8; r++) {
        const float4 pv = pp[r * 64];
        const float4 tv = tp[r * 64];
        float ps = 0.f, q1 = 0.f, q2 = 0.f, ts = 0.f, tq = 0.f;
        grp4(pv, tv, fl, sq, ab, ps, q1, q2, ts, tq);
        P += ps; Q1 += q1; Q2 += q2;
        T += ts; TQ1 += tq;
        spy  = fmaf(ps, y, spy);
        spyy = fmaf(ps, y * y, spyy);
        sty  = fmaf(ts, y, sty);
        y += 1.0f;
    }

    // Per-thread x folds: x = x0 + j
    const float sp   = P;
    const float spx  = fmaf(x0, P, Q1);
    const float spxx = fmaf(x0 * x0, P, fmaf(2.0f * x0, Q1, Q2));
    const float mass = T;
    const float stx  = fmaf(x0, T, TQ1);

    // ---- block reduction of 11 values ----
    float vals[11] = {fl, sq, ab, mass, sty, stx, sp, spy, spx, spyy, spxx};
    #pragma unroll
    for (int offm = 16; offm > 0; offm >>= 1) {
        #pragma unroll
        for (int k = 0; k < 11; k++)
            vals[k] += __shfl_down_sync(0xffffffffu, vals[k], offm);
    }
    __shared__ float smem[THREADS / 32][11];
    if (lane == 0) {
        #pragma unroll
        for (int k = 0; k < 11; k++) smem[warp][k] = vals[k];
    }
    __syncthreads();

    __shared__ bool s_last;
    if (threadIdx.x == 0) {
        float rr[11];
        #pragma unroll
        for (int k = 0; k < 11; k++) rr[k] = smem[0][k];
        for (int w = 1; w < THREADS / 32; w++)
            #pragma unroll
            for (int k = 0; k < 11; k++) rr[k] += smem[w][k];

        atomicAdd(&g_glob[0], (double)rr[0]);
        atomicAdd(&g_glob[1], (double)rr[1]);
        atomicAdd(&g_glob[2], (double)rr[2]);
        float* Pp = &g_plane[plane * 8];
        #pragma unroll
        for (int k = 0; k < 8; k++) atomicAdd(&Pp[k], rr[3 + k]);

        __threadfence();
        const unsigned cc = atomicAdd(&g_count, 1u);
        s_last = (cc == gridDim.x - 1);
    }
    __syncthreads();
    if (!s_last) return;

    // ---- last block: finalize + reset ----
    __threadfence();
    __shared__ float s_conc;
    __shared__ int   s_nv;
    if (threadIdx.x == 0) { s_conc = 0.f; s_nv = 0; }
    __syncthreads();

    for (int i = threadIdx.x; i < PLANES; i += THREADS) {
        const float* Pp = &g_plane[i * 8];
        const float m = Pp[0];
        if (m > 0.0f) {
            const float cy = Pp[1] / m;
            const float cx = Pp[2] / m;
            const float num = Pp[6] - 2.0f * cy * Pp[4] + cy * cy * Pp[3]
                            + Pp[7] - 2.0f * cx * Pp[5] + cx * cx * Pp[3];
            atomicAdd(&s_conc, num * (1.0f / 65536.0f));
            atomicAdd(&s_nv, 1);
        }
    }
    __syncthreads();

    if (threadIdx.x == 0) {
        const double N = NTOT_D;
        const float focal    = (float)(-0.6931471805599453 * g_glob[0] / N);
        const float sparsity = (float)((g_glob[1] + g_glob[2]) / N);
        const float conc     = (s_nv > 0) ? (s_conc / (float)s_nv) : 0.0f;
        out[0] = focal + 0.8f * sparsity + 1.5f * conc;
        if (out_size >= 4) { out[1] = focal; out[2] = sparsity; out[3] = conc; }
    }
    __syncthreads();

    // reset accumulators for next launch (graph replay)
    for (int i = threadIdx.x; i < PLANES * 8; i += THREADS) g_plane[i] = 0.0f;
    if (threadIdx.x < 3) g_glob[threadIdx.x] = 0.0;
    if (threadIdx.x == 0) g_count = 0u;
}

extern "C" void kernel_launch(void* const* d_in, const int* in_sizes, int n_in,
                              void* d_out, int out_size) {
    const float4* pred = (const float4*)d_in[0];
    const float4* tgt  = (const float4*)d_in[1];
    composite_kernel<<<PLANES * SUBS, THREADS>>>(pred, tgt, (float*)d_out, out_size);
}

// round 16
// speedup vs baseline: 1.1875x; 1.0610x over previous
#include <cuda_runtime.h>
#include <cuda_bf16.h>
#include <cstdint>

// CompositeLoss fused single-kernel, R15 (= R14 + missing <cstdint>):
// cp.async (LDGSTS.128) 4-stage smem ring to decouple memory-level
// parallelism from the register file. Per-thread-private staging => no
// block syncs; per-thread wait_group only. Compute core = R13
// (tanh sigmoid, 2 MUFU/elem, log2-domain focal).

#define PLANES   320          // B*C = 16*20
#define SUBS     8            // blocks per plane
#define THREADS  256          // 8 warps
#define F4_PLANE 16384        // HW/4
#define NTOT_D   20971520.0
#define STAGES   4

// Per-plane moments: [mass, sty, stx, sp, spy, spx, spyy, spxx]
__device__ float        g_plane[PLANES * 8];
// Global sums: [fl(log2-scale), sum (x-t)^2, sum |x|]
__device__ double       g_glob[3];
__device__ unsigned int g_count;

__device__ __forceinline__ float ftanh(float x) {
    float r; asm("tanh.approx.f32 %0, %1;" : "=f"(r) : "f"(x)); return r;
}
__device__ __forceinline__ float flg2(float x) {
    float r; asm("lg2.approx.f32 %0, %1;" : "=f"(r) : "f"(x)); return r;
}
__device__ __forceinline__ void cp16(unsigned int smem_dst, const void* gmem_src) {
    asm volatile("cp.async.cg.shared.global [%0], [%1], 16;"
                 :: "r"(smem_dst), "l"(gmem_src) : "memory");
}
__device__ __forceinline__ void cp_commit() {
    asm volatile("cp.async.commit_group;" ::: "memory");
}
template <int N>
__device__ __forceinline__ void cp_wait() {
    asm volatile("cp.async.wait_group %0;" :: "n"(N) : "memory");
}

// One float4 (4 elements): focal/sparsity terms + group moments.
__device__ __forceinline__ void grp4(const float4 pv, const float4 tv,
                                     float& fl, float& sq, float& ab,
                                     float& psum, float& q1, float& q2,
                                     float& tsum, float& tq1)
{
    const float xv[4] = {pv.x, pv.y, pv.z, pv.w};
    const float tt[4] = {tv.x, tv.y, tv.z, tv.w};
    float p[4];
    #pragma unroll
    for (int j = 0; j < 4; j++) {
        const float x = xv[j];
        const float t = tt[j];                        // 0.0f or 1.0f
        const float th = ftanh(x * 0.5f);             // MUFU.TANH
        const float r  = fmaf(0.5f, th, 0.5f);        // p = sigmoid(x)
        const float m  = x * -1.4426950408889634f;    // lg2(e^{-x})
        const float L  = flg2(r);                     // lg2(p)
        const float lgm1 = L + m;                     // lg2(1-p)
        const float lg = fmaf(t, -m, lgm1);           // lg2(pt)
        const float u  = fmaf(t, -th, r);             // 1 - pt
        const float a  = fmaf(t, -0.5f, 0.75f);       // alpha_t
        fl = fmaf(a * (u * u), lg, fl);               // (negative), *ln2 at end
        const float dd = x - t;
        sq = fmaf(dd, dd, sq);
        ab += fabsf(x);
        p[j] = r;
    }
    psum += (p[0] + p[1]) + (p[2] + p[3]);
    q1   += fmaf(3.0f, p[3], fmaf(2.0f, p[2], p[1]));
    q2   += fmaf(9.0f, p[3], fmaf(4.0f, p[2], p[1]));
    tsum += (tt[0] + tt[1]) + (tt[2] + tt[3]);
    tq1  += fmaf(3.0f, tt[3], fmaf(2.0f, tt[2], tt[1]));
}

__global__ __launch_bounds__(THREADS, 4) void composite_kernel(
    const float4* __restrict__ pred, const float4* __restrict__ tgt,
    float* __restrict__ out, int out_size)
{
    __shared__ float4 sP[STAGES][THREADS];
    __shared__ float4 sT[STAGES][THREADS];

    const int plane = blockIdx.x >> 3;
    const int sub   = blockIdx.x & 7;
    const int half  = sub & 1;          // column half: 0 -> [0,128), 1 -> [128,256)
    const int rb    = sub >> 1;         // row block of 64 rows
    const int warp  = threadIdx.x >> 5;
    const int lane  = threadIdx.x & 31;
    const int tid   = threadIdx.x;

    const int   row0 = rb * 64 + warp * 8;              // 8 rows per warp
    const float x0   = (float)(half * 128 + lane * 4);  // base column of this thread

    const int base = plane * F4_PLANE + row0 * 64 + half * 32 + lane;
    const float4* __restrict__ pp = pred + base;
    const float4* __restrict__ tp = tgt  + base;

    const unsigned int sp_base = (unsigned int)__cvta_generic_to_shared(&sP[0][tid]);
    const unsigned int st_base = (unsigned int)__cvta_generic_to_shared(&sT[0][tid]);
    const unsigned int stage_stride = (unsigned int)(THREADS * sizeof(float4));

    // prologue: stage rows 0..3
    #pragma unroll
    for (int s = 0; s < STAGES; s++) {
        cp16(sp_base + s * stage_stride, pp + s * 64);
        cp16(st_base + s * stage_stride, tp + s * 64);
        cp_commit();
    }

    float fl = 0.f, sq = 0.f, ab = 0.f;
    float P = 0.f, Q1 = 0.f, Q2 = 0.f;
    float spy = 0.f, spyy = 0.f;
    float T = 0.f, TQ1 = 0.f, sty = 0.f;

    float y = (float)row0;
    #pragma unroll
    for (int r = 0; r < 8; r++) {
        // issue next stage (rows 4..7) before waiting
        if (r < 4) {
            const int rn = r + 4;
            cp16(sp_base + (rn & 3) * stage_stride, pp + rn * 64);
            cp16(st_base + (rn & 3) * stage_stride, tp + rn * 64);
            cp_commit();
        }
        // wait for row r's group: pending groups after issue phase
        if      (r < 4) cp_wait<4>();
        else if (r == 4) cp_wait<3>();
        else if (r == 5) cp_wait<2>();
        else if (r == 6) cp_wait<1>();
        else             cp_wait<0>();

        const float4 pv = sP[r & 3][tid];
        const float4 tv = sT[r & 3][tid];

        float ps = 0.f, q1 = 0.f, q2 = 0.f, ts = 0.f, tq = 0.f;
        grp4(pv, tv, fl, sq, ab, ps, q1, q2, ts, tq);
        P += ps; Q1 += q1; Q2 += q2;
        T += ts; TQ1 += tq;
        spy  = fmaf(ps, y, spy);
        spyy = fmaf(ps, y * y, spyy);
        sty  = fmaf(ts, y, sty);
        y += 1.0f;
    }

    // Per-thread x folds: x = x0 + j
    const float sp   = P;
    const float spx  = fmaf(x0, P, Q1);
    const float spxx = fmaf(x0 * x0, P, fmaf(2.0f * x0, Q1, Q2));
    const float mass = T;
    const float stx  = fmaf(x0, T, TQ1);

    // ---- block reduction of 11 values ----
    float vals[11] = {fl, sq, ab, mass, sty, stx, sp, spy, spx, spyy, spxx};
    #pragma unroll
    for (int offm = 16; offm > 0; offm >>= 1) {
        #pragma unroll
        for (int k = 0; k < 11; k++)
            vals[k] += __shfl_down_sync(0xffffffffu, vals[k], offm);
    }
    __shared__ float smem[THREADS / 32][11];
    if (lane == 0) {
        #pragma unroll
        for (int k = 0; k < 11; k++) smem[warp][k] = vals[k];
    }
    __syncthreads();

    __shared__ bool s_last;
    if (threadIdx.x == 0) {
        float rr[11];
        #pragma unroll
        for (int k = 0; k < 11; k++) rr[k] = smem[0][k];
        for (int w = 1; w < THREADS / 32; w++)
            #pragma unroll
            for (int k = 0; k < 11; k++) rr[k] += smem[w][k];

        atomicAdd(&g_glob[0], (double)rr[0]);
        atomicAdd(&g_glob[1], (double)rr[1]);
        atomicAdd(&g_glob[2], (double)rr[2]);
        float* Pp = &g_plane[plane * 8];
        #pragma unroll
        for (int k = 0; k < 8; k++) atomicAdd(&Pp[k], rr[3 + k]);

        __threadfence();
        const unsigned cc = atomicAdd(&g_count, 1u);
        s_last = (cc == gridDim.x - 1);
    }
    __syncthreads();
    if (!s_last) return;

    // ---- last block: finalize + reset ----
    __threadfence();
    __shared__ float s_conc;
    __shared__ int   s_nv;
    if (threadIdx.x == 0) { s_conc = 0.f; s_nv = 0; }
    __syncthreads();

    for (int i = threadIdx.x; i < PLANES; i += THREADS) {
        const float* Pp = &g_plane[i * 8];
        const float m = Pp[0];
        if (m > 0.0f) {
            const float cy = Pp[1] / m;
            const float cx = Pp[2] / m;
            const float num = Pp[6] - 2.0f * cy * Pp[4] + cy * cy * Pp[3]
                            + Pp[7] - 2.0f * cx * Pp[5] + cx * cx * Pp[3];
            atomicAdd(&s_conc, num * (1.0f / 65536.0f));
            atomicAdd(&s_nv, 1);
        }
    }
    __syncthreads();

    if (threadIdx.x == 0) {
        const double N = NTOT_D;
        const float focal    = (float)(-0.6931471805599453 * g_glob[0] / N);
        const float sparsity = (float)((g_glob[1] + g_glob[2]) / N);
        const float conc     = (s_nv > 0) ? (s_conc / (float)s_nv) : 0.0f;
        out[0] = focal + 0.8f * sparsity + 1.5f * conc;
        if (out_size >= 4) { out[1] = focal; out[2] = sparsity; out[3] = conc; }
    }
    __syncthreads();

    // reset accumulators for next launch (graph replay)
    for (int i = threadIdx.x; i < PLANES * 8; i += THREADS) g_plane[i] = 0.0f;
    if (threadIdx.x < 3) g_glob[threadIdx.x] = 0.0;
    if (threadIdx.x == 0) g_count = 0u;
}

extern "C" void kernel_launch(void* const* d_in, const int* in_sizes, int n_in,
                              void* d_out, int out_size) {
    const float4* pred = (const float4*)d_in[0];
    const float4* tgt  = (const float4*)d_in[1];
    composite_kernel<<<PLANES * SUBS, THREADS>>>(pred, tgt, (float*)d_out, out_size);
}